// round 15
// baseline (speedup 1.0000x reference)
#include <cuda_runtime.h>
#include <cuda_bf16.h>
#include <cstdint>

#define BATCH 32
#define SEQ   512
#define DM    1024
#define NSAMP 1000
#define SPAD  1024
#define LDAH  136                        // smem row stride in halves (128 + 8 pad)
#define STG_A (64*LDAH*2)                // 17408
#define STAGE ((64+128)*LDAH*2)          // 52224: A 64 rows + B 128 rows
#define NIT   64                         // 8 nc * 8 kc
#define OFF_MM (2*STAGE)                 // 104448  float[4][64]
#define OFF_LL (OFF_MM + 1024)           // 105472  float[4][64]
#define SMEM_REQ (OFF_LL + 1024)         // 106496  -> 2 CTAs/SM

// ---------------- scratch (device globals; allocation-free rule) ----------------
__device__ __nv_bfloat16 g_Xbf[BATCH*SEQ*DM];
__device__ __nv_bfloat16 g_Wg [BATCH*SPAD*DM];
__device__ float g_biasAdj[BATCH*SPAD];
__device__ int   g_sid   [BATCH*SPAD];
__device__ float g_trueAdj[BATCH*SEQ];
__device__ float g_loss  [BATCH*SEQ];

__device__ __forceinline__ float log_q_f(int id){
    float f = (float)id;
    float p = (logf(f + 2.0f) - logf(f + 1.0f)) / 10.819798284210285f; // log(50001)
    float t = 1000.0f * log1pf(-p);
    return logf(-expm1f(t));
}

// ---------------- prelude: gather W rows -> bf16  +  exact f32 true logits + X->bf16 ----------------
__global__ void k_prep(const float* __restrict__ X, const int* __restrict__ nexts,
                       const int* __restrict__ samp, const float* __restrict__ W,
                       const float* __restrict__ bias){
    int lane = threadIdx.x & 31;
    if (blockIdx.x < 4096){
        int warp = (blockIdx.x*blockDim.x + threadIdx.x) >> 5;
        int b = warp >> 10, s = warp & 1023;
        int id = (s < NSAMP) ? samp[b*NSAMP + s] : -1;
        __nv_bfloat16* dst = g_Wg + (size_t)warp*DM;
        if (id >= 0){
            const float4* src = (const float4*)(W + (size_t)id*DM);
            #pragma unroll
            for (int j=0;j<8;j++){
                float4 v = src[lane + j*32];
                __nv_bfloat162 p0 = __floats2bfloat162_rn(v.x, v.y);
                __nv_bfloat162 p1 = __floats2bfloat162_rn(v.z, v.w);
                uint2 u; u.x = *(uint32_t*)&p0; u.y = *(uint32_t*)&p1;
                ((uint2*)dst)[lane + j*32] = u;
            }
            if (lane == 0){ g_biasAdj[warp] = bias[id] - log_q_f(id); g_sid[warp] = id; }
        } else {
            uint2 z = make_uint2(0u,0u);
            #pragma unroll
            for (int j=0;j<8;j++) ((uint2*)dst)[lane + j*32] = z;
            if (lane == 0){ g_biasAdj[warp] = -1.0e30f; g_sid[warp] = -1; }
        }
    } else {
        int g = (blockIdx.x - 4096)*8 + (threadIdx.x >> 5);
        int id = nexts[g];
        const float4* xr = (const float4*)(X + (size_t)g*DM);
        const float4* wr = (const float4*)(W + (size_t)id*DM);
        uint2* xo = (uint2*)(g_Xbf + (size_t)g*DM);
        float acc = 0.f;
        #pragma unroll
        for (int j=0;j<8;j++){
            float4 a = xr[lane + j*32], w = wr[lane + j*32];
            acc += a.x*w.x + a.y*w.y + a.z*w.z + a.w*w.w;
            __nv_bfloat162 p0 = __floats2bfloat162_rn(a.x, a.y);
            __nv_bfloat162 p1 = __floats2bfloat162_rn(a.z, a.w);
            uint2 u; u.x = *(uint32_t*)&p0; u.y = *(uint32_t*)&p1;
            xo[lane + j*32] = u;
        }
        #pragma unroll
        for (int off=16; off>0; off>>=1) acc += __shfl_xor_sync(0xffffffffu, acc, off);
        if (lane == 0) g_trueAdj[g] = acc + bias[id] - log_q_f(id);
    }
}

// ---------------- main: M=64 CTAs (2/SM), 4 warps of 64x32 tiles, online logsumexp ----------------
__device__ __forceinline__ void issue_stage(uint32_t sbase, int it,
    const __nv_bfloat16* Ag, const __nv_bfloat16* Bb, int tid){
    if (it < NIT){
        int nc = it >> 3, kc = it & 7;
        uint32_t st = sbase + (uint32_t)(it & 1)*STAGE;
        const __nv_bfloat16* gA = Ag + kc*128;
        #pragma unroll
        for (int i=0;i<8;i++){
            int idx = tid + i*128; int row = idx >> 4, c = idx & 15;
            asm volatile("cp.async.cg.shared.global [%0],[%1],16;"
                :: "r"(st + (uint32_t)(row*(LDAH*2) + c*16)), "l"(gA + (size_t)row*DM + c*8));
        }
        const __nv_bfloat16* gB = Bb + (size_t)(nc*128)*DM + kc*128;
        #pragma unroll
        for (int i=0;i<16;i++){
            int idx = tid + i*128; int row = idx >> 4, c = idx & 15;
            asm volatile("cp.async.cg.shared.global [%0],[%1],16;"
                :: "r"(st + (uint32_t)(STG_A + row*(LDAH*2) + c*16)), "l"(gB + (size_t)row*DM + c*8));
        }
    }
    asm volatile("cp.async.commit_group;");
}

__global__ __launch_bounds__(128,2)
void k_main(const int* __restrict__ nexts){
    extern __shared__ char smraw[];
    char* p = smraw;
    const uint32_t sbase = (uint32_t)__cvta_generic_to_shared(p);
    float* sMM = (float*)(p + OFF_MM);
    float* sLL = (float*)(p + OFF_LL);

    int tid = threadIdx.x, warp = tid >> 5, lane = tid & 31;
    int b    = blockIdx.x >> 3;
    int row0 = (blockIdx.x & 7) * 64;
    int n0   = warp * 32;

    const __nv_bfloat16* Ag = g_Xbf + (size_t)(b*SEQ + row0)*DM;
    const __nv_bfloat16* Bb = g_Wg  + (size_t)b*SPAD*DM;
    const float* gBias = g_biasAdj + b*SPAD;
    const int*   gSid  = g_sid    + b*SPAD;

    int tv[8];
    #pragma unroll
    for (int mi=0;mi<4;mi++)
    #pragma unroll
    for (int h=0;h<2;h++)
        tv[mi*2+h] = nexts[b*SEQ + row0 + mi*16 + h*8 + (lane>>2)];
    float m[8], l[8];
    #pragma unroll
    for (int i=0;i<8;i++){ m[i] = -3.0e38f; l[i] = 0.f; }

    issue_stage(sbase, 0, Ag, Bb, tid);

    float acc[4][4][4];
    for (int it=0; it<NIT; ++it){
        int nc = it >> 3, kc = it & 7;
        asm volatile("cp.async.wait_group 0;");
        __syncthreads();
        issue_stage(sbase, it+1, Ag, Bb, tid);

        if (kc == 0){
            #pragma unroll
            for (int mi=0;mi<4;mi++)
            #pragma unroll
            for (int j=0;j<4;j++)
            #pragma unroll
            for (int k=0;k<4;k++) acc[mi][j][k] = 0.f;
        }

        char* st = p + (it & 1)*STAGE;
        const __nv_bfloat16* A = (const __nv_bfloat16*)st;
        const __nv_bfloat16* B = (const __nv_bfloat16*)(st + STG_A);

        #pragma unroll
        for (int kk=0; kk<8; kk++){
            uint32_t af[4][4];
            #pragma unroll
            for (int mi=0;mi<4;mi++){
                const __nv_bfloat16* q = A + (mi*16 + (lane & 15))*LDAH + kk*16 + (lane >> 4)*8;
                uint32_t sa = (uint32_t)__cvta_generic_to_shared(q);
                asm volatile("ldmatrix.sync.aligned.m8n8.x4.shared.b16 {%0,%1,%2,%3},[%4];"
                    : "=r"(af[mi][0]), "=r"(af[mi][1]), "=r"(af[mi][2]), "=r"(af[mi][3]) : "r"(sa));
            }
            uint32_t bf[4][2];
            #pragma unroll
            for (int j=0;j<4;j+=2){
                const __nv_bfloat16* q = B + (n0 + j*8 + (lane & 7) + (lane >> 4)*8)*LDAH
                                           + kk*16 + ((lane >> 3) & 1)*8;
                uint32_t sb = (uint32_t)__cvta_generic_to_shared(q);
                asm volatile("ldmatrix.sync.aligned.m8n8.x4.shared.b16 {%0,%1,%2,%3},[%4];"
                    : "=r"(bf[j][0]), "=r"(bf[j][1]), "=r"(bf[j+1][0]), "=r"(bf[j+1][1]) : "r"(sb));
            }
            #pragma unroll
            for (int mi=0;mi<4;mi++)
            #pragma unroll
            for (int j=0;j<4;j++){
                asm volatile("mma.sync.aligned.m16n8k16.row.col.f32.bf16.bf16.f32 "
                    "{%0,%1,%2,%3},{%4,%5,%6,%7},{%8,%9},{%0,%1,%2,%3};"
                    : "+f"(acc[mi][j][0]), "+f"(acc[mi][j][1]), "+f"(acc[mi][j][2]), "+f"(acc[mi][j][3])
                    : "r"(af[mi][0]), "r"(af[mi][1]), "r"(af[mi][2]), "r"(af[mi][3]),
                      "r"(bf[j][0]), "r"(bf[j][1]));
            }
        }

        if (kc == 7){
            int cb = nc*128 + n0 + (lane & 3)*2;
            float2 bi[4]; int2 si[4];
            #pragma unroll
            for (int j=0;j<4;j++){
                bi[j] = *(const float2*)&gBias[cb + j*8];  // L2-resident, shared by 8 CTAs
                si[j] = *(const int2*)  &gSid [cb + j*8];
            }
            #pragma unroll
            for (int mi=0;mi<4;mi++)
            #pragma unroll
            for (int h=0;h<2;h++){
                int ri = mi*2 + h;
                float bm = -3.0e38f;
                #pragma unroll
                for (int j=0;j<4;j++){
                    float v0 = acc[mi][j][2*h]   + bi[j].x; if (si[j].x == tv[ri]) v0 = -1.0e9f;
                    float v1 = acc[mi][j][2*h+1] + bi[j].y; if (si[j].y == tv[ri]) v1 = -1.0e9f;
                    acc[mi][j][2*h] = v0; acc[mi][j][2*h+1] = v1;
                    bm = fmaxf(bm, fmaxf(v0, v1));
                }
                float nm = fmaxf(m[ri], bm);
                float s = l[ri] * __expf(m[ri] - nm);
                #pragma unroll
                for (int j=0;j<4;j++)
                    s += __expf(acc[mi][j][2*h] - nm) + __expf(acc[mi][j][2*h+1] - nm);
                l[ri] = s; m[ri] = nm;
            }
        }
    }

    // quad merge (lanes share rows across cols)
    #pragma unroll
    for (int o=1; o<=2; o<<=1){
        #pragma unroll
        for (int i=0;i<8;i++){
            float om = __shfl_xor_sync(0xffffffffu, m[i], o);
            float ol = __shfl_xor_sync(0xffffffffu, l[i], o);
            float nm = fmaxf(m[i], om);
            l[i] = l[i]*__expf(m[i]-nm) + ol*__expf(om-nm);
            m[i] = nm;
        }
    }
    if ((lane & 3) == 0){
        #pragma unroll
        for (int mi=0;mi<4;mi++)
        #pragma unroll
        for (int h=0;h<2;h++){
            int row = mi*16 + h*8 + (lane>>2);
            sMM[warp*64 + row] = m[mi*2+h];
            sLL[warp*64 + row] = l[mi*2+h];
        }
    }
    __syncthreads();
    if (tid < 64){
        float M = -3.0e38f, L = 0.f;
        #pragma unroll
        for (int w=0; w<4; w++){
            float mw = sMM[w*64 + tid], lw = sLL[w*64 + tid];
            float nm = fmaxf(M, mw);
            L = L*__expf(M-nm) + lw*__expf(mw-nm);
            M = nm;
        }
        float ta = g_trueAdj[b*SEQ + row0 + tid];
        float fm = fmaxf(M, ta);
        float FL = L*__expf(M-fm) + __expf(ta-fm);
        g_loss[b*SEQ + row0 + tid] = logf(FL) + fm - ta;
    }
}

// ---------------- mean ----------------
__global__ void k_final(float* out){
    __shared__ float ss[256];
    float s = 0.f;
    for (int i=threadIdx.x; i<BATCH*SEQ; i+=256) s += g_loss[i];
    ss[threadIdx.x] = s; __syncthreads();
    for (int o=128; o>0; o>>=1){
        if (threadIdx.x < o) ss[threadIdx.x] += ss[threadIdx.x + o];
        __syncthreads();
    }
    if (threadIdx.x == 0) out[0] = 0.5f * ss[0] / (float)(BATCH*SEQ);
}

extern "C" void kernel_launch(void* const* d_in, const int* in_sizes, int n_in,
                              void* d_out, int out_size){
    const float* X     = (const float*)d_in[0];
    const int*   nexts = (const int*)  d_in[1];
    const int*   samp  = (const int*)  d_in[2];
    const float* W     = (const float*)d_in[3];
    const float* bias  = (const float*)d_in[4];
    float* out = (float*)d_out;

    cudaFuncSetAttribute(k_main, cudaFuncAttributeMaxDynamicSharedMemorySize, SMEM_REQ);

    k_prep <<<4096 + 2048, 256>>>(X, nexts, samp, W, bias);
    k_main <<<BATCH*8, 128, SMEM_REQ>>>(nexts);
    k_final<<<1, 256>>>(out);
}

// round 16
// speedup vs baseline: 1.6175x; 1.6175x over previous
#include <cuda_runtime.h>
#include <cuda_bf16.h>
#include <cstdint>

#define BATCH 32
#define SEQ   512
#define DM    1024
#define NSAMP 1000
#define SPAD  1024
#define LDAH  136                        // smem row stride in halves (128 + 8 pad)
#define STAGE_BYTES ((128+256)*LDAH*2)   // 104448: A 128 rows + B 256 rows
#define NIT   32                         // 4 nc * 8 kc
#define OFF_BIAS (2*STAGE_BYTES)         // 208896
#define OFF_SID  (OFF_BIAS + 4096)       // 212992
#define OFF_MM   (OFF_SID  + 4096)       // 217088  float[4][128]
#define OFF_LL   (OFF_MM   + 2048)       // 219136
#define SMEM_REQ (OFF_LL + 2048)         // 221184

// ---------------- scratch (device globals; allocation-free rule) ----------------
__device__ __nv_bfloat16 g_Xbf[BATCH*SEQ*DM];
__device__ __nv_bfloat16 g_Wg [BATCH*SPAD*DM];
__device__ float g_biasAdj[BATCH*SPAD];
__device__ int   g_sid   [BATCH*SPAD];
__device__ float g_trueAdj[BATCH*SEQ];
__device__ float g_sum   = 0.f;          // cross-CTA loss accumulator (self-resetting)
__device__ int   g_count = 0;            // completion counter (self-resetting)

__device__ __forceinline__ float log_q_f(int id){
    float f = (float)id;
    float p = (logf(f + 2.0f) - logf(f + 1.0f)) / 10.819798284210285f; // log(50001)
    float t = 1000.0f * log1pf(-p);
    return logf(-expm1f(t));
}

// ---------------- prelude: gather W rows -> bf16  +  exact f32 true logits + X->bf16 ----------------
__global__ void k_prep(const float* __restrict__ X, const int* __restrict__ nexts,
                       const int* __restrict__ samp, const float* __restrict__ W,
                       const float* __restrict__ bias){
    int lane = threadIdx.x & 31;
    if (blockIdx.x < 4096){
        int warp = (blockIdx.x*blockDim.x + threadIdx.x) >> 5;
        int b = warp >> 10, s = warp & 1023;
        int id = (s < NSAMP) ? samp[b*NSAMP + s] : -1;
        __nv_bfloat16* dst = g_Wg + (size_t)warp*DM;
        if (id >= 0){
            const float4* src = (const float4*)(W + (size_t)id*DM);
            #pragma unroll
            for (int j=0;j<8;j++){
                float4 v = src[lane + j*32];
                __nv_bfloat162 p0 = __floats2bfloat162_rn(v.x, v.y);
                __nv_bfloat162 p1 = __floats2bfloat162_rn(v.z, v.w);
                uint2 u; u.x = *(uint32_t*)&p0; u.y = *(uint32_t*)&p1;
                ((uint2*)dst)[lane + j*32] = u;
            }
            if (lane == 0){ g_biasAdj[warp] = bias[id] - log_q_f(id); g_sid[warp] = id; }
        } else {
            uint2 z = make_uint2(0u,0u);
            #pragma unroll
            for (int j=0;j<8;j++) ((uint2*)dst)[lane + j*32] = z;
            if (lane == 0){ g_biasAdj[warp] = -1.0e30f; g_sid[warp] = -1; }
        }
    } else {
        int g = (blockIdx.x - 4096)*8 + (threadIdx.x >> 5);
        int id = nexts[g];
        const float4* xr = (const float4*)(X + (size_t)g*DM);
        const float4* wr = (const float4*)(W + (size_t)id*DM);
        uint2* xo = (uint2*)(g_Xbf + (size_t)g*DM);
        float acc = 0.f;
        #pragma unroll
        for (int j=0;j<8;j++){
            float4 a = xr[lane + j*32], w = wr[lane + j*32];
            acc += a.x*w.x + a.y*w.y + a.z*w.z + a.w*w.w;
            __nv_bfloat162 p0 = __floats2bfloat162_rn(a.x, a.y);
            __nv_bfloat162 p1 = __floats2bfloat162_rn(a.z, a.w);
            uint2 u; u.x = *(uint32_t*)&p0; u.y = *(uint32_t*)&p1;
            xo[lane + j*32] = u;
        }
        #pragma unroll
        for (int off=16; off>0; off>>=1) acc += __shfl_xor_sync(0xffffffffu, acc, off);
        if (lane == 0) g_trueAdj[g] = acc + bias[id] - log_q_f(id);
    }
}

// ---------------- main: mma.sync GEMM, 64x64 warp tiles, fused online logsumexp ----------------
// grid 128 (4 CTAs/batch, M=128). 8 warps in a 2(M)x4(N) grid of 64x64 tiles.
// N-chunk=256 (nc=0..3), K-chunk=128 (kc=0..7), 2-stage cp.async double buffer.
__device__ __forceinline__ void issue_stage(uint32_t sbase, int it,
    const __nv_bfloat16* Ag, const __nv_bfloat16* Bb, int tid){
    if (it < NIT){
        int nc = it >> 3, kc = it & 7;
        uint32_t st = sbase + (uint32_t)(it & 1)*STAGE_BYTES;
        int rb = tid >> 4, c8 = tid & 15;
        uint32_t d0 = st + (uint32_t)(rb*(LDAH*2) + c8*16);
        const __nv_bfloat16* gA = Ag + (size_t)rb*DM + kc*128 + c8*8;
        const __nv_bfloat16* gB = Bb + (size_t)(nc*256 + rb)*DM + kc*128 + c8*8;
        #pragma unroll
        for (int i=0;i<8;i++)
            asm volatile("cp.async.cg.shared.global [%0],[%1],16;"
                :: "r"(d0 + (uint32_t)(i*16*(LDAH*2))), "l"(gA + (size_t)(i*16)*DM));
        uint32_t d1 = d0 + (uint32_t)(128*(LDAH*2));
        #pragma unroll
        for (int i=0;i<16;i++)
            asm volatile("cp.async.cg.shared.global [%0],[%1],16;"
                :: "r"(d1 + (uint32_t)(i*16*(LDAH*2))), "l"(gB + (size_t)(i*16)*DM));
    }
    asm volatile("cp.async.commit_group;");
}

__global__ __launch_bounds__(256,1)
void k_main(const int* __restrict__ nexts, float* __restrict__ out){
    extern __shared__ char smraw[];
    char* p = smraw;
    const uint32_t sbase = (uint32_t)__cvta_generic_to_shared(p);
    float* sBias = (float*)(p + OFF_BIAS);
    int*   sSid  = (int*)  (p + OFF_SID);
    float* sMM   = (float*)(p + OFF_MM);
    float* sLL   = (float*)(p + OFF_LL);

    int tid = threadIdx.x, warp = tid >> 5, lane = tid & 31;
    int cta = blockIdx.x, b = cta >> 2, row0 = (cta & 3) << 7;
    int m0 = (warp >> 2) * 64, n0 = (warp & 3) * 64;

    for (int i=tid; i<SPAD; i+=256){ sBias[i] = g_biasAdj[b*SPAD+i]; sSid[i] = g_sid[b*SPAD+i]; }

    const __nv_bfloat16* Ag = g_Xbf + (size_t)(b*SEQ + row0)*DM;
    const __nv_bfloat16* Bb = g_Wg  + (size_t)b*SPAD*DM;

    int tv[8];
    #pragma unroll
    for (int mi=0;mi<4;mi++)
    #pragma unroll
    for (int h=0;h<2;h++)
        tv[mi*2+h] = nexts[b*SEQ + row0 + m0 + mi*16 + h*8 + (lane>>2)];
    float m[8], l[8];
    #pragma unroll
    for (int i=0;i<8;i++){ m[i] = -3.0e38f; l[i] = 0.f; }

    issue_stage(sbase, 0, Ag, Bb, tid);

    float acc[4][8][4];
    for (int it=0; it<NIT; ++it){
        int nc = it >> 3, kc = it & 7;
        asm volatile("cp.async.wait_group 0;");
        __syncthreads();
        issue_stage(sbase, it+1, Ag, Bb, tid);

        if (kc == 0){
            #pragma unroll
            for (int mi=0;mi<4;mi++)
            #pragma unroll
            for (int j=0;j<8;j++)
            #pragma unroll
            for (int k=0;k<4;k++) acc[mi][j][k] = 0.f;
        }

        char* st = p + (it & 1)*STAGE_BYTES;
        const __nv_bfloat16* A = (const __nv_bfloat16*)st;
        const __nv_bfloat16* B = (const __nv_bfloat16*)(st + 128*LDAH*2);

        #pragma unroll
        for (int kk=0; kk<8; kk++){
            uint32_t af[4][4];
            #pragma unroll
            for (int mi=0;mi<4;mi++){
                const __nv_bfloat16* q = A + (m0 + mi*16 + (lane & 15))*LDAH + kk*16 + (lane >> 4)*8;
                uint32_t sa = (uint32_t)__cvta_generic_to_shared(q);
                asm volatile("ldmatrix.sync.aligned.m8n8.x4.shared.b16 {%0,%1,%2,%3},[%4];"
                    : "=r"(af[mi][0]), "=r"(af[mi][1]), "=r"(af[mi][2]), "=r"(af[mi][3]) : "r"(sa));
            }
            uint32_t bf[8][2];
            #pragma unroll
            for (int j=0;j<8;j+=2){
                const __nv_bfloat16* q = B + (n0 + j*8 + (lane & 7) + (lane >> 4)*8)*LDAH
                                           + kk*16 + ((lane >> 3) & 1)*8;
                uint32_t sb = (uint32_t)__cvta_generic_to_shared(q);
                asm volatile("ldmatrix.sync.aligned.m8n8.x4.shared.b16 {%0,%1,%2,%3},[%4];"
                    : "=r"(bf[j][0]), "=r"(bf[j][1]), "=r"(bf[j+1][0]), "=r"(bf[j+1][1]) : "r"(sb));
            }
            #pragma unroll
            for (int mi=0;mi<4;mi++)
            #pragma unroll
            for (int j=0;j<8;j++){
                asm volatile("mma.sync.aligned.m16n8k16.row.col.f32.bf16.bf16.f32 "
                    "{%0,%1,%2,%3},{%4,%5,%6,%7},{%8,%9},{%0,%1,%2,%3};"
                    : "+f"(acc[mi][j][0]), "+f"(acc[mi][j][1]), "+f"(acc[mi][j][2]), "+f"(acc[mi][j][3])
                    : "r"(af[mi][0]), "r"(af[mi][1]), "r"(af[mi][2]), "r"(af[mi][3]),
                      "r"(bf[j][0]), "r"(bf[j][1]));
            }
        }

        if (kc == 7){
            int cb = nc*256 + n0 + (lane & 3)*2;
            float2 bi[8]; int2 si[8];
            #pragma unroll
            for (int j=0;j<8;j++){
                bi[j] = *(const float2*)&sBias[cb + j*8];
                si[j] = *(const int2*)  &sSid [cb + j*8];
            }
            #pragma unroll
            for (int mi=0;mi<4;mi++)
            #pragma unroll
            for (int h=0;h<2;h++){
                int ri = mi*2 + h;
                float bm = -3.0e38f;
                #pragma unroll
                for (int j=0;j<8;j++){
                    float v0 = acc[mi][j][2*h]   + bi[j].x; if (si[j].x == tv[ri]) v0 = -1.0e9f;
                    float v1 = acc[mi][j][2*h+1] + bi[j].y; if (si[j].y == tv[ri]) v1 = -1.0e9f;
                    acc[mi][j][2*h] = v0; acc[mi][j][2*h+1] = v1;
                    bm = fmaxf(bm, fmaxf(v0, v1));
                }
                float nm = fmaxf(m[ri], bm);
                float s = l[ri] * __expf(m[ri] - nm);
                #pragma unroll
                for (int j=0;j<8;j++)
                    s += __expf(acc[mi][j][2*h] - nm) + __expf(acc[mi][j][2*h+1] - nm);
                l[ri] = s; m[ri] = nm;
            }
        }
    }

    // merge across the 4 lanes of each quad (same rows, different cols)
    #pragma unroll
    for (int o=1; o<=2; o<<=1){
        #pragma unroll
        for (int i=0;i<8;i++){
            float om = __shfl_xor_sync(0xffffffffu, m[i], o);
            float ol = __shfl_xor_sync(0xffffffffu, l[i], o);
            float nm = fmaxf(m[i], om);
            l[i] = l[i]*__expf(m[i]-nm) + ol*__expf(om-nm);
            m[i] = nm;
        }
    }
    if ((lane & 3) == 0){
        #pragma unroll
        for (int mi=0;mi<4;mi++)
        #pragma unroll
        for (int h=0;h<2;h++){
            int row = m0 + mi*16 + h*8 + (lane>>2);
            sMM[(warp & 3)*128 + row] = m[mi*2+h];
            sLL[(warp & 3)*128 + row] = l[mi*2+h];
        }
    }
    __syncthreads();

    // per-row loss, then deterministic in-CTA reduction of the 128 losses
    float loss = 0.f;
    if (tid < 128){
        float M0 = sMM[tid],     L0 = sLL[tid];
        float M1 = sMM[128+tid], L1 = sLL[128+tid];
        float M2 = sMM[256+tid], L2 = sLL[256+tid];
        float M3 = sMM[384+tid], L3 = sLL[384+tid];
        float nm = fmaxf(fmaxf(M0,M1), fmaxf(M2,M3));
        float L  = L0*__expf(M0-nm) + L1*__expf(M1-nm) + L2*__expf(M2-nm) + L3*__expf(M3-nm);
        float ta = g_trueAdj[b*SEQ + row0 + tid];
        float fm = fmaxf(nm, ta);
        float FL = L*__expf(nm-fm) + __expf(ta-fm);
        loss = logf(FL) + fm - ta;
    }
    __syncthreads();
    #pragma unroll
    for (int o=16; o>0; o>>=1) loss += __shfl_xor_sync(0xffffffffu, loss, o);
    if (tid < 128 && lane == 0) sLL[warp] = loss;
    __syncthreads();
    if (tid == 0){
        float ctasum = sLL[0] + sLL[1] + sLL[2] + sLL[3];
        atomicAdd(&g_sum, ctasum);
        __threadfence();
        int old = atomicAdd(&g_count, 1);
        if (old == gridDim.x - 1){
            float tot = atomicAdd(&g_sum, 0.0f);   // all adds visible (fenced before count)
            out[0] = 0.5f * tot / (float)(BATCH*SEQ);
            __threadfence();
            g_sum = 0.f;                            // self-reset for next graph replay
            g_count = 0;
        }
    }
}

extern "C" void kernel_launch(void* const* d_in, const int* in_sizes, int n_in,
                              void* d_out, int out_size){
    const float* X     = (const float*)d_in[0];
    const int*   nexts = (const int*)  d_in[1];
    const int*   samp  = (const int*)  d_in[2];
    const float* W     = (const float*)d_in[3];
    const float* bias  = (const float*)d_in[4];
    float* out = (float*)d_out;

    cudaFuncSetAttribute(k_main, cudaFuncAttributeMaxDynamicSharedMemorySize, SMEM_REQ);

    k_prep <<<4096 + 2048, 256>>>(X, nexts, samp, W, bias);
    k_main <<<BATCH*4, 256, SMEM_REQ>>>(nexts, out);
}